// round 9
// baseline (speedup 1.0000x reference)
#include <cuda_runtime.h>
#include <cuda_bf16.h>
#include <math.h>
#include <stdint.h>

// Problem constants
#define BSZ   4096
#define LAT   64
#define FRAME 512
#define HID   1024
#define NE    8
#define GH    128
#define IN1   576    // LAT+FRAME
#define IN2   1088   // LAT+HID
#define NOUT  512
#define K0R   (NE*IN1)     // 4608
#define K12R  (NE*IN2)     // 8704
#define K0P   (K0R + 32)   // 4640 (bias fold + pad)
#define K12P  (K12R + 32)  // 8736

// ---------------- device scratch (static; no cudaMalloc) ------------------
__device__ float g_coef[BSZ * NE];
__device__ __nv_bfloat16 g_xh0[BSZ * IN1], g_xl0[BSZ * IN1]; // concat(z,c) hi/lo
__device__ __nv_bfloat16 g_xh [BSZ * IN2], g_xl [BSZ * IN2]; // layer0 out hi/lo
__device__ __nv_bfloat16 g_xh2[BSZ * IN2], g_xl2[BSZ * IN2]; // layer1 out hi/lo
__device__ __nv_bfloat16 g_wth[(size_t)HID * K12P];          // W^T hi (+bias fold)
__device__ __nv_bfloat16 g_wtl[(size_t)HID * K12P];          // W^T lo

// ======================= PTX helpers (plain sm_103-safe) ==================
__device__ __forceinline__ uint32_t smem_u32(const void* p) {
    uint32_t a;
    asm("{ .reg .u64 t; cvta.to.shared.u64 t, %1; cvt.u32.u64 %0, t; }"
        : "=r"(a) : "l"(p));
    return a;
}
#define LDSM_X4(r0, r1, r2, r3, addr) \
    asm volatile("ldmatrix.sync.aligned.m8n8.x4.shared.b16 {%0,%1,%2,%3}, [%4];" \
                 : "=r"(r0), "=r"(r1), "=r"(r2), "=r"(r3) : "r"(addr))
#define MMA_BF16(c, a, b) \
    asm volatile("mma.sync.aligned.m16n8k16.row.col.f32.bf16.bf16.f32 " \
                 "{%0,%1,%2,%3}, {%4,%5,%6,%7}, {%8,%9}, {%0,%1,%2,%3};" \
                 : "+f"((c)[0]), "+f"((c)[1]), "+f"((c)[2]), "+f"((c)[3]) \
                 : "r"((a)[0]), "r"((a)[1]), "r"((a)[2]), "r"((a)[3]), \
                   "r"((b)[0]), "r"((b)[1]))
#define CP_ASYNC16(dst, src) \
    asm volatile("cp.async.cg.shared.global [%0], [%1], 16;" :: "r"(dst), "l"(src))
#define CP_COMMIT() asm volatile("cp.async.commit_group;" ::: "memory")
#define CP_WAIT1()  asm volatile("cp.async.wait_group 1;" ::: "memory")

__device__ __forceinline__ void split4(float4 a, uint2& h, uint2& l) {
    __nv_bfloat162 h01 = __floats2bfloat162_rn(a.x, a.y);
    __nv_bfloat162 h23 = __floats2bfloat162_rn(a.z, a.w);
    __nv_bfloat162 l01 = __floats2bfloat162_rn(a.x - __bfloat162float(h01.x),
                                               a.y - __bfloat162float(h01.y));
    __nv_bfloat162 l23 = __floats2bfloat162_rn(a.z - __bfloat162float(h23.x),
                                               a.w - __bfloat162float(h23.y));
    h.x = *reinterpret_cast<uint32_t*>(&h01);
    h.y = *reinterpret_cast<uint32_t*>(&h23);
    l.x = *reinterpret_cast<uint32_t*>(&l01);
    l.y = *reinterpret_cast<uint32_t*>(&l23);
}
// scale 2 packed bf16(hi,lo) values by cf, re-split
__device__ __forceinline__ void scale_split2(uint32_t hb, uint32_t lb, float cf,
                                             uint32_t& oh, uint32_t& ol) {
    __nv_bfloat162 h2 = *reinterpret_cast<__nv_bfloat162*>(&hb);
    __nv_bfloat162 l2 = *reinterpret_cast<__nv_bfloat162*>(&lb);
    float a = cf * (__bfloat162float(h2.x) + __bfloat162float(l2.x));
    float b = cf * (__bfloat162float(h2.y) + __bfloat162float(l2.y));
    __nv_bfloat162 hh = __floats2bfloat162_rn(a, b);
    __nv_bfloat162 ll = __floats2bfloat162_rn(a - __bfloat162float(hh.x),
                                              b - __bfloat162float(hh.y));
    oh = *reinterpret_cast<uint32_t*>(&hh);
    ol = *reinterpret_cast<uint32_t*>(&ll);
}
__device__ __forceinline__ void fsplit2(float a, float b, uint32_t& oh, uint32_t& ol) {
    __nv_bfloat162 hh = __floats2bfloat162_rn(a, b);
    __nv_bfloat162 ll = __floats2bfloat162_rn(a - __bfloat162float(hh.x),
                                              b - __bfloat162float(hh.y));
    oh = *reinterpret_cast<uint32_t*>(&hh);
    ol = *reinterpret_cast<uint32_t*>(&ll);
}

// ======================= gate MLP -> softmax coef =========================
#define GROWS 4
__global__ __launch_bounds__(128) void gate_kernel(
    const float* __restrict__ z, const float* __restrict__ c,
    const float* __restrict__ gw1, const float* __restrict__ gb1,
    const float* __restrict__ gw2, const float* __restrict__ gb2,
    const float* __restrict__ gw3, const float* __restrict__ gb3)
{
    __shared__ float sx[GROWS][IN1];
    __shared__ float sh[GROWS][GH];
    const int tid = threadIdx.x;
    const int b0  = blockIdx.x * GROWS;

    for (int r = 0; r < GROWS; r++) {
        int b = b0 + r;
        for (int i = tid; i < LAT;   i += 128) sx[r][i]       = z[b * LAT + i];
        for (int i = tid; i < FRAME; i += 128) sx[r][LAT + i] = c[b * FRAME + i];
    }
    __syncthreads();

    float acc[GROWS];
    #pragma unroll
    for (int r = 0; r < GROWS; r++) acc[r] = gb1[tid];
    for (int i = 0; i < IN1; i++) {
        float g = gw1[i * GH + tid];
        #pragma unroll
        for (int r = 0; r < GROWS; r++) acc[r] += sx[r][i] * g;
    }
    #pragma unroll
    for (int r = 0; r < GROWS; r++)
        sh[r][tid] = acc[r] > 0.f ? acc[r] : expm1f(acc[r]);
    __syncthreads();

    float acc2[GROWS];
    #pragma unroll
    for (int r = 0; r < GROWS; r++) acc2[r] = gb2[tid];
    for (int i = 0; i < GH; i++) {
        float g = gw2[i * GH + tid];
        #pragma unroll
        for (int r = 0; r < GROWS; r++) acc2[r] += sh[r][i] * g;
    }
    __syncthreads();
    #pragma unroll
    for (int r = 0; r < GROWS; r++)
        sh[r][tid] = acc2[r] > 0.f ? acc2[r] : expm1f(acc2[r]);
    __syncthreads();

    const int r = tid >> 5, lane = tid & 31;
    float lacc[NE];
    #pragma unroll
    for (int e = 0; e < NE; e++) lacc[e] = 0.f;
    for (int i = lane; i < GH; i += 32) {
        float h = sh[r][i];
        #pragma unroll
        for (int e = 0; e < NE; e++) lacc[e] += h * gw3[i * NE + e];
    }
    #pragma unroll
    for (int e = 0; e < NE; e++)
        #pragma unroll
        for (int o = 16; o > 0; o >>= 1)
            lacc[e] += __shfl_down_sync(0xffffffffu, lacc[e], o);
    if (lane == 0) {
        float logit[NE]; float mx = -1e30f;
        #pragma unroll
        for (int e = 0; e < NE; e++) { logit[e] = lacc[e] + gb3[e]; mx = fmaxf(mx, logit[e]); }
        float s = 0.f;
        #pragma unroll
        for (int e = 0; e < NE; e++) { logit[e] = expf(logit[e] - mx); s += logit[e]; }
        float inv = 1.f / s;
        int b = b0 + r;
        #pragma unroll
        for (int e = 0; e < NE; e++) g_coef[b * NE + e] = logit[e] * inv;
    }
}

// ---- fill: split z/c; write z prefixes of all x buffers ------------------
__global__ void fill_kernel(const float* __restrict__ z, const float* __restrict__ c)
{
    int idx = blockIdx.x * blockDim.x + threadIdx.x;
    int nz = BSZ * (LAT / 4);
    if (idx < nz) {
        int b = idx / (LAT / 4), i4 = idx % (LAT / 4);
        float4 v = reinterpret_cast<const float4*>(&z[b * LAT])[i4];
        uint2 h, l; split4(v, h, l);
        reinterpret_cast<uint2*>(&g_xh0[b * IN1])[i4] = h;
        reinterpret_cast<uint2*>(&g_xl0[b * IN1])[i4] = l;
        reinterpret_cast<uint2*>(&g_xh [b * IN2])[i4] = h;
        reinterpret_cast<uint2*>(&g_xl [b * IN2])[i4] = l;
        reinterpret_cast<uint2*>(&g_xh2[b * IN2])[i4] = h;
        reinterpret_cast<uint2*>(&g_xl2[b * IN2])[i4] = l;
        return;
    }
    idx -= nz;
    int nc = BSZ * (FRAME / 4);
    if (idx < nc) {
        int b = idx / (FRAME / 4), i4 = idx % (FRAME / 4);
        float4 v = reinterpret_cast<const float4*>(&c[b * FRAME])[i4];
        uint2 h, l; split4(v, h, l);
        reinterpret_cast<uint2*>(&g_xh0[b * IN1 + LAT])[i4] = h;
        reinterpret_cast<uint2*>(&g_xl0[b * IN1 + LAT])[i4] = l;
    }
}

// ---- weight prep: wt[n][k] = split(Wflat[k][n]), k<K; bias[e][n] at K+e --
__global__ __launch_bounds__(256) void prep_kernel(
    const float* __restrict__ W, const float* __restrict__ bias,
    int K, int Nl, int Kpad)
{
    __shared__ float ts[32][33];
    const int kx = blockIdx.x, ny = blockIdx.y;
    const int tx = threadIdx.x & 31, ty = threadIdx.x >> 5;
    const int n0 = ny * 32;
    const int Kt = K / 32;
    if (kx < Kt) {
        const int k0 = kx * 32;
        #pragma unroll
        for (int rr = 0; rr < 4; rr++) {
            int k = k0 + ty + rr * 8;
            ts[ty + rr * 8][tx] = W[(size_t)k * Nl + n0 + tx];
        }
        __syncthreads();
        #pragma unroll
        for (int rr = 0; rr < 4; rr++) {
            int n = n0 + ty + rr * 8;
            float v = ts[tx][ty + rr * 8];
            __nv_bfloat16 h = __float2bfloat16(v);
            float lo = v - __bfloat162float(h);
            size_t off = (size_t)n * Kpad + k0 + tx;
            g_wth[off] = h;
            g_wtl[off] = __float2bfloat16(lo);
        }
    } else {
        #pragma unroll
        for (int rr = 0; rr < 4; rr++) {
            int n = n0 + ty + rr * 8;
            float v = (tx < NE) ? bias[tx * Nl + n] : 0.f;
            __nv_bfloat16 h = __float2bfloat16(v);
            float lo = v - __bfloat162float(h);
            size_t off = (size_t)n * Kpad + K + tx;
            g_wth[off] = h;
            g_wtl[off] = __float2bfloat16(lo);
        }
    }
}

// ====== fused-mix split-bf16 GEMM: BM=BN=128, BK=32, 256 thr, 2 CTA/SM ====
// C[b,n] = sum_k A[b,k] Wt[n,k];  A[b, e*IN+i] = coef[b,e]*x[b,i] (loader),
// A[b, K+e] = coef[b,e] (bias fold), 0 pad.  3-term: AhBh + AhBl + AlBh.
#define BMg 128
#define BNg 128
#define BKg 32
#define APITCH 40                  // bf16 per smem row (80B)
#define TILE_BF (128 * APITCH)     // 5120 bf16 (10240 B)
#define STAGE_BF (4 * TILE_BF)     // Ah, Al, Bh, Bl
#define SMEM_BYTES (2 * STAGE_BF * 2)   // 81920

__global__ __launch_bounds__(256, 2) void gemm_fused_kernel(
    const __nv_bfloat16* __restrict__ xh, const __nv_bfloat16* __restrict__ xl,
    int xp, int INw, int Kreal, int Kpad,
    const __nv_bfloat16* __restrict__ wth, const __nv_bfloat16* __restrict__ wtl,
    float* __restrict__ outf, __nv_bfloat16* __restrict__ oxh,
    __nv_bfloat16* __restrict__ oxl, int opitch, int ooff, int do_elu)
{
    extern __shared__ __nv_bfloat16 smem[];
    const uint32_t sb = smem_u32(smem);
    char* smc = reinterpret_cast<char*>(smem);
    const int tid  = threadIdx.x;
    const int lane = tid & 31;
    const int wid  = tid >> 5;
    const int warp_m = wid & 3;
    const int warp_n = wid >> 2;
    const int bm = blockIdx.y * BMg;
    const int bn = blockIdx.x * BNg;

    float C[2][8][4];
    #pragma unroll
    for (int tm = 0; tm < 2; tm++)
        #pragma unroll
        for (int tn = 0; tn < 8; tn++)
            #pragma unroll
            for (int u = 0; u < 4; u++) C[tm][tn][u] = 0.f;

    // ldmatrix per-lane byte offsets (pitch 80B)
    const int a_r  = (lane & 7) + ((lane >> 3) & 1) * 8;
    const int a_ko = (lane >> 4) * 16;
    const uint32_t aoff = a_r * 80 + a_ko;
    const int b_r  = (lane & 7) + (lane >> 4) * 8;
    const int b_ko = ((lane >> 3) & 1) * 16;
    const uint32_t boff = b_r * 80 + b_ko;

    const int niter = Kpad / BKg;

    // loader: A synthesized (LDG+scale+split+STS), B via cp.async.
    // unit: t = tid + j*256 in [0,512): row = t>>2 (128), q = t&3 (8 bf16 = 16B)
    auto loadstage = [&](int it, int s) {
        const int k0 = it * BKg;
        const uint32_t stb = sb + s * (STAGE_BF * 2);
        char* stc = smc + s * (STAGE_BF * 2);
        const bool ezone = (k0 < Kreal);
        int e = 0, ib = 0;
        if (ezone) { e = k0 / INw; ib = k0 - e * INw; }
        #pragma unroll
        for (int j = 0; j < 2; j++) {
            int t = tid + j * 256;
            int row = t >> 2, q = t & 3;
            uint32_t so = (row * APITCH + q * 8) * 2;
            // B: cp.async
            const __nv_bfloat16* bhp = wth + (size_t)(bn + row) * Kpad + k0 + q * 8;
            const __nv_bfloat16* blp = wtl + (size_t)(bn + row) * Kpad + k0 + q * 8;
            CP_ASYNC16(stb + TILE_BF * 4 + so, bhp);
            CP_ASYNC16(stb + TILE_BF * 6 + so, blp);
            // A: synthesize
            uint4 oh, ol;
            if (ezone) {
                float cf = g_coef[(bm + row) * NE + e];
                const __nv_bfloat16* ap = xh + (size_t)(bm + row) * xp + ib + q * 8;
                const __nv_bfloat16* alp = xl + (size_t)(bm + row) * xp + ib + q * 8;
                uint4 h4 = *reinterpret_cast<const uint4*>(ap);
                uint4 l4 = *reinterpret_cast<const uint4*>(alp);
                scale_split2(h4.x, l4.x, cf, oh.x, ol.x);
                scale_split2(h4.y, l4.y, cf, oh.y, ol.y);
                scale_split2(h4.z, l4.z, cf, oh.z, ol.z);
                scale_split2(h4.w, l4.w, cf, oh.w, ol.w);
            } else {
                if (q == 0) {
                    const float* crow = g_coef + (size_t)(bm + row) * NE;
                    fsplit2(crow[0], crow[1], oh.x, ol.x);
                    fsplit2(crow[2], crow[3], oh.y, ol.y);
                    fsplit2(crow[4], crow[5], oh.z, ol.z);
                    fsplit2(crow[6], crow[7], oh.w, ol.w);
                } else {
                    oh = make_uint4(0, 0, 0, 0);
                    ol = make_uint4(0, 0, 0, 0);
                }
            }
            *reinterpret_cast<uint4*>(stc + so) = oh;
            *reinterpret_cast<uint4*>(stc + TILE_BF * 2 + so) = ol;
        }
    };

    loadstage(0, 0);
    CP_COMMIT();

    for (int i = 0; i < niter; i++) {
        if (i + 1 < niter) loadstage(i + 1, (i + 1) & 1);
        CP_COMMIT();
        CP_WAIT1();
        __syncthreads();

        const int s = i & 1;
        const uint32_t sAh = sb + s * (STAGE_BF * 2);
        const uint32_t sAl = sAh + TILE_BF * 2;
        const uint32_t sBh = sAl + TILE_BF * 2;
        const uint32_t sBl = sBh + TILE_BF * 2;

        #pragma unroll
        for (int ks = 0; ks < 2; ks++) {
            uint32_t ah[2][4], al[2][4];
            #pragma unroll
            for (int tm = 0; tm < 2; tm++) {
                uint32_t base = (warp_m * 32 + tm * 16) * 80 + ks * 32;
                LDSM_X4(ah[tm][0], ah[tm][1], ah[tm][2], ah[tm][3], sAh + base + aoff);
                LDSM_X4(al[tm][0], al[tm][1], al[tm][2], al[tm][3], sAl + base + aoff);
            }
            #pragma unroll
            for (int g = 0; g < 4; g++) {
                uint32_t bh[4], bl[4];
                uint32_t base = (warp_n * 64 + g * 16) * 80 + ks * 32;
                LDSM_X4(bh[0], bh[1], bh[2], bh[3], sBh + base + boff);
                LDSM_X4(bl[0], bl[1], bl[2], bl[3], sBl + base + boff);
                #pragma unroll
                for (int tm = 0; tm < 2; tm++)
                    #pragma unroll
                    for (int half = 0; half < 2; half++) {
                        int tn = g * 2 + half;
                        const uint32_t* bph = &bh[half * 2];
                        const uint32_t* bpl = &bl[half * 2];
                        MMA_BF16(C[tm][tn], ah[tm], bph);
                        MMA_BF16(C[tm][tn], ah[tm], bpl);
                        MMA_BF16(C[tm][tn], al[tm], bph);
                    }
            }
        }
        __syncthreads();
    }

    // ---- epilogue: mixed output. ELU + split-bf16 (or fp32 d_out) ----
    #pragma unroll
    for (int tm = 0; tm < 2; tm++) {
        int m0 = bm + warp_m * 32 + tm * 16 + (lane >> 2);
        #pragma unroll
        for (int tn = 0; tn < 8; tn++) {
            int n0 = bn + warp_n * 64 + tn * 8 + (lane & 3) * 2;
            float v0 = C[tm][tn][0], v1 = C[tm][tn][1];
            float v2 = C[tm][tn][2], v3 = C[tm][tn][3];
            if (do_elu) {
                v0 = v0 > 0.f ? v0 : expm1f(v0);
                v1 = v1 > 0.f ? v1 : expm1f(v1);
                v2 = v2 > 0.f ? v2 : expm1f(v2);
                v3 = v3 > 0.f ? v3 : expm1f(v3);
            }
            if (outf) {
                *reinterpret_cast<float2*>(outf + (size_t)m0 * opitch + ooff + n0) =
                    make_float2(v0, v1);
                *reinterpret_cast<float2*>(outf + (size_t)(m0 + 8) * opitch + ooff + n0) =
                    make_float2(v2, v3);
            } else {
                uint32_t h0, l0, h1, l1;
                fsplit2(v0, v1, h0, l0);
                fsplit2(v2, v3, h1, l1);
                size_t o0 = (size_t)m0 * opitch + ooff + n0;
                size_t o1 = (size_t)(m0 + 8) * opitch + ooff + n0;
                *reinterpret_cast<uint32_t*>(oxh + o0) = h0;
                *reinterpret_cast<uint32_t*>(oxl + o0) = l0;
                *reinterpret_cast<uint32_t*>(oxh + o1) = h1;
                *reinterpret_cast<uint32_t*>(oxl + o1) = l1;
            }
        }
    }
}

// ================================ launch ==================================
extern "C" void kernel_launch(void* const* d_in, const int* in_sizes, int n_in,
                              void* d_out, int out_size)
{
    const float* z   = (const float*)d_in[0];
    const float* c   = (const float*)d_in[1];
    const float* w0  = (const float*)d_in[2];
    const float* b0  = (const float*)d_in[3];
    const float* w1  = (const float*)d_in[4];
    const float* b1  = (const float*)d_in[5];
    const float* w2  = (const float*)d_in[6];
    const float* b2  = (const float*)d_in[7];
    const float* gw1 = (const float*)d_in[8];
    const float* gb1 = (const float*)d_in[9];
    const float* gw2 = (const float*)d_in[10];
    const float* gb2 = (const float*)d_in[11];
    const float* gw3 = (const float*)d_in[12];
    const float* gb3 = (const float*)d_in[13];
    float* out = (float*)d_out;

    __nv_bfloat16 *xh0, *xl0, *xh, *xl, *xh2, *xl2, *wth, *wtl;
    cudaGetSymbolAddress((void**)&xh0, g_xh0);
    cudaGetSymbolAddress((void**)&xl0, g_xl0);
    cudaGetSymbolAddress((void**)&xh,  g_xh);
    cudaGetSymbolAddress((void**)&xl,  g_xl);
    cudaGetSymbolAddress((void**)&xh2, g_xh2);
    cudaGetSymbolAddress((void**)&xl2, g_xl2);
    cudaGetSymbolAddress((void**)&wth, g_wth);
    cudaGetSymbolAddress((void**)&wtl, g_wtl);

    cudaFuncSetAttribute(gemm_fused_kernel,
                         cudaFuncAttributeMaxDynamicSharedMemorySize, SMEM_BYTES);

    gate_kernel<<<BSZ / GROWS, 128>>>(z, c, gw1, gb1, gw2, gb2, gw3, gb3);
    {
        int total = BSZ * (LAT / 4) + BSZ * (FRAME / 4);
        fill_kernel<<<(total + 255) / 256, 256>>>(z, c);
    }

    // ---- layer 0: K=4608(+32), N=HID; out -> xh/xl[:, LAT:] ----
    {
        dim3 pg(K0R / 32 + 1, HID / 32);
        prep_kernel<<<pg, 256>>>(w0, b0, K0R, HID, K0P);
        dim3 grid(HID / BNg, BSZ / BMg);
        gemm_fused_kernel<<<grid, 256, SMEM_BYTES>>>(
            xh0, xl0, IN1, IN1, K0R, K0P, wth, wtl,
            nullptr, xh, xl, IN2, LAT, 1);
    }
    // ---- layer 1: K=8704(+32), N=HID; out -> xh2/xl2[:, LAT:] ----
    {
        dim3 pg(K12R / 32 + 1, HID / 32);
        prep_kernel<<<pg, 256>>>(w1, b1, K12R, HID, K12P);
        dim3 grid(HID / BNg, BSZ / BMg);
        gemm_fused_kernel<<<grid, 256, SMEM_BYTES>>>(
            xh, xl, IN2, IN2, K12R, K12P, wth, wtl,
            nullptr, xh2, xl2, IN2, LAT, 1);
    }
    // ---- layer 2: K=8704(+32), N=NOUT; out -> d_out fp32 ----
    {
        dim3 pg(K12R / 32 + 1, NOUT / 32);
        prep_kernel<<<pg, 256>>>(w2, b2, K12R, NOUT, K12P);
        dim3 grid(NOUT / BNg, BSZ / BMg);
        gemm_fused_kernel<<<grid, 256, SMEM_BYTES>>>(
            xh2, xl2, IN2, IN2, K12R, K12P, wth, wtl,
            out, nullptr, nullptr, NOUT, 0, 0);
    }
}